// round 14
// baseline (speedup 1.0000x reference)
#include <cuda_runtime.h>
#include <cuda_bf16.h>
#include <cstdint>
#include <math.h>

// ---------------------------------------------------------------------------
// SimpleModelQ collapsed. TWO kernels + memset reset nodes.
//   qk[b] = (M @ archi[b] + c)/sqrt(258);  M = kW^T qW, c = kW^T qb
//   (q.kb score shift constant per batch -> cancels in softmax; kb unused)
//   fbar = softmax-weighted feat mean.
//   WEIGHT FOLD: h1 = relu(W1@(vW@fbar+vb)+b1) = relu(Weq@fbar + beq),
//   Weq = W1@vW, beq = W1@vb + b1  (input-independent -> computed inside the
//   attention kernel, overlapped with its DRAM-bound tail).
//   Then h2 = relu(W2@h1+b2); out = W3@h2+b3.
// attn: 256 CTAs = 128 b x 2 S-halves, reg double-buffered LDG, warp-local
//       online softmax; after epilogue each CTA computes a Weq tile.
// mlp:  phase1 h1 (K=255, direct store) -> gsync -> phase2 h2 (atomic
//       split-K) -> who-elected tail. ONE gsync total.
// ---------------------------------------------------------------------------

#define S_     1024
#define LAST_  258
#define FEAT_  255
#define NCTA_  256

// ---- device scratch ----
__device__ float4 g_qkp[64 * 256];      // k0 stage-1 partials
__device__ float  g_uT[256 * 256];      // [f][2b+half] unnormalized sums
__device__ float2 g_ml[256];            // [2b+half] (m, l)
__device__ float  g_weq[512 * 256];     // Weq[n][f] (f padded to 256); memset 0
__device__ float  g_beq[512];           // W1@vb + b1
__device__ float  g_h1[512 * 128];      // written directly (post-relu)
__device__ float  g_h2[256 * 128];      // atomic-accumulated; memset 0/launch
__device__ int    g_sync[8];            // memset 0/launch

__device__ __forceinline__ unsigned long long dup_f32(float a) {
    unsigned long long r;
    asm("mov.b64 %0, {%1, %1};" : "=l"(r) : "f"(a));
    return r;
}
__device__ __forceinline__ void fma_x2(unsigned long long& acc,
                                       unsigned long long a, unsigned long long w) {
    asm("fma.rn.f32x2 %0, %1, %2, %0;" : "+l"(acc) : "l"(a), "l"(w));
}
__device__ __forceinline__ void mul_x2(unsigned long long& d, unsigned long long a,
                                       unsigned long long b) {
    asm("mul.rn.f32x2 %0, %1, %2;" : "=l"(d) : "l"(a), "l"(b));
}
__device__ __forceinline__ void unpack_x2(unsigned long long v, float& lo, float& hi) {
    asm("mov.b64 {%0, %1}, %2;" : "=f"(lo), "=f"(hi) : "l"(v));
}

__device__ __forceinline__ void gsync(int i) {
    __syncthreads();
    if (threadIdx.x == 0) {
        __threadfence();
        atomicAdd(&g_sync[i], 1);
        while (*(volatile int*)&g_sync[i] < NCTA_) { }
        __threadfence();
    }
    __syncthreads();
}

// ===========================================================================
// ATTENTION kernel: k0 + flash pooling + Weq/beq weight-fold tiles.
// ===========================================================================
__global__ void __launch_bounds__(256, 2)
attn_kernel(const float* __restrict__ input,
            const float* __restrict__ kW, const float* __restrict__ qW,
            const float* __restrict__ qb,
            const float* __restrict__ vW, const float* __restrict__ vb,
            const float* __restrict__ W1, const float* __restrict__ b1) {
    __shared__ float qk[264];
    __shared__ float red[8 * 256];      // epilogue scratch / W1 tile / vb stage
    __shared__ float2 mlw[8];
    __shared__ float sw[64];
    const int c    = blockIdx.x;
    const int tid  = threadIdx.x;
    const int lane = tid & 31, w = tid >> 5;
    const int ab = c >> 1, half = c & 1;
    const float* gbase = input + (size_t)ab * S_ * LAST_;
    const float* pbase = gbase + (size_t)(half * 512) * LAST_ + lane * 2;

    // ---------- prefetch attention chunk 0 (overlaps k0 phase) ----------
    unsigned long long xA[4][4], xB[4][4];
    {
        const float* rp = pbase + (size_t)(w * 4) * LAST_;
#pragma unroll
        for (int i = 0; i < 4; i++)
#pragma unroll
            for (int j = 0; j < 4; j++)
                xA[i][j] = *(const unsigned long long*)(rp + (size_t)i * LAST_ + j * 64);
    }
    const float ar0 = gbase[FEAT_ + 0];
    const float ar1 = gbase[FEAT_ + 1];
    const float ar2 = gbase[FEAT_ + 2];

    // ---------- k0 partials (CTAs 0..63, 16 h-rows each) ----------
    if (c < 64) {
        const int h0 = c * 16;
        if (tid < 64) {
            int hh = h0 + (tid >> 2), k = tid & 3;
            sw[tid] = (k < 3) ? qW[hh * 3 + k] : qb[hh];
        }
        __syncthreads();
        float m0 = 0.f, m1 = 0.f, m2 = 0.f, cc2 = 0.f;
        if (tid < FEAT_) {
#pragma unroll
            for (int i = 0; i < 16; i++) {
                float kv = kW[(size_t)(h0 + i) * FEAT_ + tid];
                m0 += kv * sw[i * 4 + 0];
                m1 += kv * sw[i * 4 + 1];
                m2 += kv * sw[i * 4 + 2];
                cc2 += kv * sw[i * 4 + 3];
            }
        }
        g_qkp[c * 256 + tid] = make_float4(m0, m1, m2, cc2);
    }
    gsync(0);

    // ---------- qk vector: every CTA reduces all 64 partials (L2-hot) ----------
    {
        float4 s = make_float4(0.f, 0.f, 0.f, 0.f);
#pragma unroll 8
        for (int p = 0; p < 64; p++) {
            float4 v = g_qkp[p * 256 + tid];
            s.x += v.x; s.y += v.y; s.z += v.z; s.w += v.w;
        }
        float val = (s.x * ar0 + s.y * ar1 + s.z * ar2 + s.w) * rsqrtf(258.0f);
        qk[tid] = (tid < FEAT_) ? val : 0.f;
    }
    __syncthreads();

    unsigned long long q2[4];
#pragma unroll
    for (int j = 0; j < 4; j++)
        q2[j] = *(const unsigned long long*)(qk + j * 64 + lane * 2);

    // ---------- mainloop: warp-local online softmax, zero barriers ----------
    float m_w = -INFINITY, l_w = 0.f;
    unsigned long long acc[4] = {0ull, 0ull, 0ull, 0ull};

    auto loadc = [&](unsigned long long (&x)[4][4], int ch) {
        const float* rp = pbase + (size_t)(ch * 32 + w * 4) * LAST_;
#pragma unroll
        for (int i = 0; i < 4; i++)
#pragma unroll
            for (int j = 0; j < 4; j++)
                x[i][j] = *(const unsigned long long*)(rp + (size_t)i * LAST_ + j * 64);
    };
    auto process = [&](unsigned long long (&x)[4][4]) {
        float v[4];
#pragma unroll
        for (int i = 0; i < 4; i++) {
            unsigned long long va = 0ull;
#pragma unroll
            for (int j = 0; j < 4; j++) fma_x2(va, x[i][j], q2[j]);
            float lo, hi; unpack_x2(va, lo, hi);
            v[i] = lo + hi;
        }
#pragma unroll
        for (int o = 16; o; o >>= 1) {
#pragma unroll
            for (int i = 0; i < 4; i++)
                v[i] += __shfl_xor_sync(0xffffffffu, v[i], o);
        }
        float mc = fmaxf(fmaxf(v[0], v[1]), fmaxf(v[2], v[3]));
        float mnew  = fmaxf(m_w, mc);
        float alpha = __expf(m_w - mnew);
        float p0 = __expf(v[0] - mnew), p1 = __expf(v[1] - mnew);
        float p2 = __expf(v[2] - mnew), p3 = __expf(v[3] - mnew);
        l_w = l_w * alpha + (p0 + p1) + (p2 + p3);
        m_w = mnew;
        unsigned long long ap = dup_f32(alpha);
#pragma unroll
        for (int j = 0; j < 4; j++) mul_x2(acc[j], acc[j], ap);
        unsigned long long pp0 = dup_f32(p0), pp1 = dup_f32(p1);
        unsigned long long pp2 = dup_f32(p2), pp3 = dup_f32(p3);
#pragma unroll
        for (int j = 0; j < 4; j++) {
            fma_x2(acc[j], pp0, x[0][j]);
            fma_x2(acc[j], pp1, x[1][j]);
            fma_x2(acc[j], pp2, x[2][j]);
            fma_x2(acc[j], pp3, x[3][j]);
        }
    };

    for (int cc = 0; cc < 8; cc++) {
        loadc(xB, 2 * cc + 1);
        process(xA);
        if (cc < 7) loadc(xA, 2 * cc + 2);
        process(xB);
    }

    // ---------- epilogue: merge 8 warps -> (M, L, u) ----------
#pragma unroll
    for (int j = 0; j < 4; j++)
        *(unsigned long long*)(red + w * 256 + j * 64 + lane * 2) = acc[j];
    if (lane == 0) mlw[w] = make_float2(m_w, l_w);
    __syncthreads();
    {
        float M = -INFINITY;
#pragma unroll
        for (int ww = 0; ww < 8; ww++) M = fmaxf(M, mlw[ww].x);
        float L = 0.f, u = 0.f;
#pragma unroll
        for (int ww = 0; ww < 8; ww++) {
            float e = __expf(mlw[ww].x - M);
            L += e * mlw[ww].y;
            u += e * red[ww * 256 + tid];
        }
        g_uT[(size_t)tid * 256 + c] = u;       // [f][2b+half]
        if (tid == 0) g_ml[c] = make_float2(M, L);
    }
    __syncthreads();   // epilogue done reading red

    // ---------- Weq tile: Weq = W1 @ vW, atomic split-K ----------
    // 256 CTAs = 64 n-blocks (8 n) x 4 k-splits (256 k).
    {
        const int n0 = (c >> 2) * 8, k0 = (c & 3) * 256;
#pragma unroll
        for (int j = 0; j < 8; j++) {
            int idx = j * 256 + tid;
            int nn = idx & 7, kk = idx >> 3;
            red[kk * 8 + nn] = W1[(size_t)(n0 + nn) * 1024 + k0 + kk];
        }
        __syncthreads();
        if (tid < FEAT_) {
            unsigned long long a4[4] = {0ull, 0ull, 0ull, 0ull};
            for (int t = 0; t < 256; t += 16) {
                float vv[16];
#pragma unroll
                for (int i = 0; i < 16; i++)
                    vv[i] = vW[(size_t)(k0 + t + i) * FEAT_ + tid];
#pragma unroll
                for (int i = 0; i < 16; i++) {
                    unsigned long long ap = dup_f32(vv[i]);
                    const float* wp = &red[(t + i) * 8];
                    fma_x2(a4[0], ap, *(const unsigned long long*)(wp + 0));
                    fma_x2(a4[1], ap, *(const unsigned long long*)(wp + 2));
                    fma_x2(a4[2], ap, *(const unsigned long long*)(wp + 4));
                    fma_x2(a4[3], ap, *(const unsigned long long*)(wp + 6));
                }
            }
#pragma unroll
            for (int i = 0; i < 4; i++) {
                float lo, hi; unpack_x2(a4[i], lo, hi);
                atomicAdd(&g_weq[(size_t)(n0 + 2 * i) * 256 + tid], lo);
                atomicAdd(&g_weq[(size_t)(n0 + 2 * i + 1) * 256 + tid], hi);
            }
        }
    }

    // ---------- beq = W1 @ vb + b1 (CTAs 0,1: 256 n each) ----------
    if (c < 2) {
        __syncthreads();
        for (int j = tid; j < 1024; j += 256) red[j] = vb[j];
        __syncthreads();
        const int n = c * 256 + tid;
        float s = b1[n];
        for (int t = 0; t < 1024; t += 16) {
            float wv[16];
#pragma unroll
            for (int i = 0; i < 16; i++)
                wv[i] = W1[(size_t)n * 1024 + t + i];
#pragma unroll
            for (int i = 0; i < 16; i++) s += wv[i] * red[t + i];
        }
        g_beq[n] = s;
    }
}

// ===========================================================================
// MLP kernel: h1 = relu(Weq@fbar + beq) -> gsync -> h2 -> tail.
// ===========================================================================
__global__ void __launch_bounds__(256, 2)
mlp_kernel(const float* __restrict__ W2, const float* __restrict__ b2,
           const float* __restrict__ W3, const float* __restrict__ b3,
           float* __restrict__ out) {
    __shared__ __align__(16) float smw[256 * 10];
    __shared__ float sqk[264];
    __shared__ int who;
    const int c   = blockIdx.x;
    const int tid = threadIdx.x;
    const int b   = tid & 127, h = tid >> 7;

    // ---------- phase 1: h1[n][b] = relu(Weq@fbar + beq), 2 n per CTA ----------
    {
        float2 ml0 = g_ml[2 * b], ml1 = g_ml[2 * b + 1];
        float M  = fmaxf(ml0.x, ml1.x);
        float e0 = __expf(ml0.x - M), e1 = __expf(ml1.x - M);
        float invL = 1.0f / (e0 * ml0.y + e1 * ml1.y);
        float s0 = e0 * invL, s1 = e1 * invL;

        const int n0 = c * 2;
        smw[tid * 2 + 0] = g_weq[(size_t)n0 * 256 + tid];
        smw[tid * 2 + 1] = g_weq[(size_t)(n0 + 1) * 256 + tid];
        __syncthreads();

        float a1 = 0.f;
        for (int t = 0; t < 256; t += 16) {
            float2 uv[16];
#pragma unroll
            for (int i = 0; i < 16; i++)
                uv[i] = *(const float2*)(g_uT + (size_t)(t + i) * 256 + 2 * b);
#pragma unroll
            for (int i = 0; i < 16; i++)
                a1 += (s0 * uv[i].x + s1 * uv[i].y) * smw[(t + i) * 2 + h];
        }
        const int n = n0 + h;
        g_h1[(size_t)n * 128 + b] = fmaxf(a1 + g_beq[n], 0.f);
    }
    gsync(2);

    // ---------- phase 2: h2 partials, atomic split-K ----------
    {
        const int n0 = (c >> 3) * 8, ks = c & 7, k0 = ks * 64;
        if (tid < 64) {
#pragma unroll
            for (int nn = 0; nn < 8; nn++)
                smw[tid * 10 + nn] = W2[(size_t)(n0 + nn) * 512 + k0 + tid];
        }
        __syncthreads();
        unsigned long long a2[2] = {0ull, 0ull};
        for (int t = 0; t < 64; t += 16) {
            float av[16];
#pragma unroll
            for (int i = 0; i < 16; i++)
                av[i] = g_h1[(size_t)(k0 + t + i) * 128 + b];
#pragma unroll
            for (int i = 0; i < 16; i++) {
                unsigned long long ap = dup_f32(av[i]);
                const float* wp = &smw[(t + i) * 10 + h * 4];
                fma_x2(a2[0], ap, *(const unsigned long long*)(wp + 0));
                fma_x2(a2[1], ap, *(const unsigned long long*)(wp + 2));
            }
        }
#pragma unroll
        for (int i = 0; i < 2; i++) {
            float lo, hi; unpack_x2(a2[i], lo, hi);
            int n = n0 + h * 4 + 2 * i;
            atomicAdd(&g_h2[(size_t)n * 128 + b], lo);
            atomicAdd(&g_h2[(size_t)(n + 1) * 128 + b], hi);
        }
    }

    // ---------- phase 3: last-arriving CTA computes the final layer ----------
    __threadfence();
    __syncthreads();
    if (tid == 0) who = atomicAdd(&g_sync[4], 1);
    __syncthreads();
    if (who == NCTA_ - 1) {
        __threadfence();
        smw[tid]       = W3[tid];
        smw[256 + tid] = W3[256 + tid];
        sqk[tid]       = b2[tid];
        __syncthreads();
        if (tid < 128) {
            float o0 = 0.f, o1 = 0.f;
            for (int t = 0; t < 256; t += 16) {
                float hv[16];
#pragma unroll
                for (int i = 0; i < 16; i++)
                    hv[i] = g_h2[(size_t)(t + i) * 128 + tid];
#pragma unroll
                for (int i = 0; i < 16; i++) {
                    float hh = fmaxf(hv[i] + sqk[t + i], 0.f);
                    o0 += hh * smw[t + i];
                    o1 += hh * smw[256 + t + i];
                }
            }
            ((float2*)out)[tid] = make_float2(o0 + b3[0], o1 + b3[1]);
        }
    }
}

// ===========================================================================
extern "C" void kernel_launch(void* const* d_in, const int* in_sizes, int n_in,
                              void* d_out, int out_size) {
    const float* input = (const float*)d_in[0];
    const float* kW = (const float*)d_in[1];
    // d_in[2] = kb: constant score shift per batch -> cancels in softmax
    const float* vW = (const float*)d_in[3];
    const float* vb = (const float*)d_in[4];
    const float* qW = (const float*)d_in[5];
    const float* qb = (const float*)d_in[6];
    const float* W1 = (const float*)d_in[7];
    const float* b1 = (const float*)d_in[8];
    const float* W2 = (const float*)d_in[9];
    const float* b2 = (const float*)d_in[10];
    const float* W3 = (const float*)d_in[11];
    const float* b3 = (const float*)d_in[12];
    float* out = (float*)d_out;

    void *p_sync, *p_h2, *p_weq;
    cudaGetSymbolAddress(&p_sync, g_sync);
    cudaGetSymbolAddress(&p_h2, g_h2);
    cudaGetSymbolAddress(&p_weq, g_weq);
    cudaMemsetAsync(p_sync, 0, 8 * sizeof(int));
    cudaMemsetAsync(p_h2, 0, 256 * 128 * sizeof(float));
    cudaMemsetAsync(p_weq, 0, 512 * 256 * sizeof(float));

    attn_kernel<<<NCTA_, 256>>>(input, kW, qW, qb, vW, vb, W1, b1);
    mlp_kernel<<<NCTA_, 256>>>(W2, b2, W3, b3, out);
}

// round 16
// speedup vs baseline: 2.9819x; 2.9819x over previous
#include <cuda_runtime.h>
#include <cuda_bf16.h>
#include <cstdint>
#include <math.h>

// ---------------------------------------------------------------------------
// SimpleModelQ collapsed. ONE fused kernel + memset reset nodes.
//   qk[b] = (M @ archi[b] + c)/sqrt(258);  M = kW^T qW, c = kW^T qb
//   (q.kb score shift constant per batch -> cancels in softmax; kb unused)
//   fbar = softmax-weighted feat mean; res=vW@fbar+vb; h1=relu(W1@res+b1);
//   h2=relu(W2@h1+b2); out=W3@h2+b3.
// 256 CTAs x 256 thr, 2 CTAs/SM. Attention: reg double-buffered LDG +
// warp-local online softmax (zero mainloop barriers). MLP: forced-MLP16
// K loops, software-pipelined with ONE canonical ping-pong idiom,
// atomic split-K. 4 gsyncs + who-elected tail.
// ---------------------------------------------------------------------------

#define S_     1024
#define LAST_  258
#define FEAT_  255
#define NCTA_  256

// ---- device scratch ----
__device__ float4 g_qkp[64 * 256];      // k0 stage-1 partials
__device__ float  g_uT[256 * 256];      // [f][2b+half] unnormalized sums
__device__ float2 g_ml[256];            // [2b+half] (m, l)
__device__ float  g_res[1024 * 128];
__device__ float  g_h1[512 * 128];      // atomic-accumulated; memset 0/launch
__device__ float  g_h2[256 * 128];      // atomic-accumulated; memset 0/launch
__device__ int    g_sync[8];            // memset 0/launch

__device__ __forceinline__ unsigned long long dup_f32(float a) {
    unsigned long long r;
    asm("mov.b64 %0, {%1, %1};" : "=l"(r) : "f"(a));
    return r;
}
__device__ __forceinline__ void fma_x2(unsigned long long& acc,
                                       unsigned long long a, unsigned long long w) {
    asm("fma.rn.f32x2 %0, %1, %2, %0;" : "+l"(acc) : "l"(a), "l"(w));
}
__device__ __forceinline__ void mul_x2(unsigned long long& d, unsigned long long a,
                                       unsigned long long b) {
    asm("mul.rn.f32x2 %0, %1, %2;" : "=l"(d) : "l"(a), "l"(b));
}
__device__ __forceinline__ void unpack_x2(unsigned long long v, float& lo, float& hi) {
    asm("mov.b64 {%0, %1}, %2;" : "=f"(lo), "=f"(hi) : "l"(v));
}

__device__ __forceinline__ void gsync(int i) {
    __syncthreads();
    if (threadIdx.x == 0) {
        __threadfence();
        atomicAdd(&g_sync[i], 1);
        while (*(volatile int*)&g_sync[i] < NCTA_) { }
        __threadfence();
    }
    __syncthreads();
}

__global__ void __launch_bounds__(256, 2)
fused_kernel(const float* __restrict__ input,
             const float* __restrict__ kW, const float* __restrict__ qW,
             const float* __restrict__ qb,
             const float* __restrict__ vW, const float* __restrict__ vb,
             const float* __restrict__ W1, const float* __restrict__ b1,
             const float* __restrict__ W2, const float* __restrict__ b2,
             const float* __restrict__ W3, const float* __restrict__ b3,
             float* __restrict__ out) {
    __shared__ float qk[264];
    __shared__ float red[8 * 256];
    __shared__ float2 mlw[8];
    __shared__ float sw[64];
    __shared__ __align__(16) float smw[256 * 18];
    __shared__ float sqk[264];
    __shared__ int who;
    const int c    = blockIdx.x;
    const int tid  = threadIdx.x;
    const int lane = tid & 31, w = tid >> 5;
    const int ab = c >> 1, half = c & 1;
    const float* gbase = input + (size_t)ab * S_ * LAST_;
    const float* pbase = gbase + (size_t)(half * 512) * LAST_ + lane * 2;

    // ---------- prefetch attention chunk 0 (overlaps k0 phase) ----------
    unsigned long long xA[4][4], xB[4][4];
    {
        const float* rp = pbase + (size_t)(w * 4) * LAST_;
#pragma unroll
        for (int i = 0; i < 4; i++)
#pragma unroll
            for (int j = 0; j < 4; j++)
                xA[i][j] = *(const unsigned long long*)(rp + (size_t)i * LAST_ + j * 64);
    }
    const float ar0 = gbase[FEAT_ + 0];
    const float ar1 = gbase[FEAT_ + 1];
    const float ar2 = gbase[FEAT_ + 2];

    // ---------- k0 partials (CTAs 0..63, 16 h-rows each) ----------
    if (c < 64) {
        const int h0 = c * 16;
        if (tid < 64) {
            int hh = h0 + (tid >> 2), k = tid & 3;
            sw[tid] = (k < 3) ? qW[hh * 3 + k] : qb[hh];
        }
        __syncthreads();
        float m0 = 0.f, m1 = 0.f, m2 = 0.f, cc2 = 0.f;
        if (tid < FEAT_) {
#pragma unroll
            for (int i = 0; i < 16; i++) {
                float kv = kW[(size_t)(h0 + i) * FEAT_ + tid];
                m0 += kv * sw[i * 4 + 0];
                m1 += kv * sw[i * 4 + 1];
                m2 += kv * sw[i * 4 + 2];
                cc2 += kv * sw[i * 4 + 3];
            }
        }
        g_qkp[c * 256 + tid] = make_float4(m0, m1, m2, cc2);
    }
    gsync(0);

    // ---------- qk vector: every CTA reduces all 64 partials (L2-hot) ----------
    {
        float4 s = make_float4(0.f, 0.f, 0.f, 0.f);
#pragma unroll 8
        for (int p = 0; p < 64; p++) {
            float4 v = g_qkp[p * 256 + tid];
            s.x += v.x; s.y += v.y; s.z += v.z; s.w += v.w;
        }
        float val = (s.x * ar0 + s.y * ar1 + s.z * ar2 + s.w) * rsqrtf(258.0f);
        qk[tid] = (tid < FEAT_) ? val : 0.f;
    }
    __syncthreads();

    unsigned long long q2[4];
#pragma unroll
    for (int j = 0; j < 4; j++)
        q2[j] = *(const unsigned long long*)(qk + j * 64 + lane * 2);

    // ---------- attention mainloop: warp-local softmax, zero barriers ----------
    float m_w = -INFINITY, l_w = 0.f;
    unsigned long long acc[4] = {0ull, 0ull, 0ull, 0ull};

    auto loadc = [&](unsigned long long (&x)[4][4], int ch) {
        const float* rp = pbase + (size_t)(ch * 32 + w * 4) * LAST_;
#pragma unroll
        for (int i = 0; i < 4; i++)
#pragma unroll
            for (int j = 0; j < 4; j++)
                x[i][j] = *(const unsigned long long*)(rp + (size_t)i * LAST_ + j * 64);
    };
    auto process = [&](unsigned long long (&x)[4][4]) {
        float v[4];
#pragma unroll
        for (int i = 0; i < 4; i++) {
            unsigned long long va = 0ull;
#pragma unroll
            for (int j = 0; j < 4; j++) fma_x2(va, x[i][j], q2[j]);
            float lo, hi; unpack_x2(va, lo, hi);
            v[i] = lo + hi;
        }
#pragma unroll
        for (int o = 16; o; o >>= 1) {
#pragma unroll
            for (int i = 0; i < 4; i++)
                v[i] += __shfl_xor_sync(0xffffffffu, v[i], o);
        }
        float mc = fmaxf(fmaxf(v[0], v[1]), fmaxf(v[2], v[3]));
        float mnew  = fmaxf(m_w, mc);
        float alpha = __expf(m_w - mnew);
        float p0 = __expf(v[0] - mnew), p1 = __expf(v[1] - mnew);
        float p2 = __expf(v[2] - mnew), p3 = __expf(v[3] - mnew);
        l_w = l_w * alpha + (p0 + p1) + (p2 + p3);
        m_w = mnew;
        unsigned long long ap = dup_f32(alpha);
#pragma unroll
        for (int j = 0; j < 4; j++) mul_x2(acc[j], acc[j], ap);
        unsigned long long pp0 = dup_f32(p0), pp1 = dup_f32(p1);
        unsigned long long pp2 = dup_f32(p2), pp3 = dup_f32(p3);
#pragma unroll
        for (int j = 0; j < 4; j++) {
            fma_x2(acc[j], pp0, x[0][j]);
            fma_x2(acc[j], pp1, x[1][j]);
            fma_x2(acc[j], pp2, x[2][j]);
            fma_x2(acc[j], pp3, x[3][j]);
        }
    };

    for (int cc = 0; cc < 8; cc++) {
        loadc(xB, 2 * cc + 1);
        process(xA);
        if (cc < 7) loadc(xA, 2 * cc + 2);
        process(xB);
    }

    // ---------- attention epilogue: merge 8 warps -> (M, L, u) ----------
#pragma unroll
    for (int j = 0; j < 4; j++)
        *(unsigned long long*)(red + w * 256 + j * 64 + lane * 2) = acc[j];
    if (lane == 0) mlw[w] = make_float2(m_w, l_w);
    __syncthreads();
    {
        float M = -INFINITY;
#pragma unroll
        for (int ww = 0; ww < 8; ww++) M = fmaxf(M, mlw[ww].x);
        float L = 0.f, u = 0.f;
#pragma unroll
        for (int ww = 0; ww < 8; ww++) {
            float e = __expf(mlw[ww].x - M);
            L += e * mlw[ww].y;
            u += e * red[ww * 256 + tid];
        }
        g_uT[(size_t)tid * 256 + c] = u;       // [f][2b+half]
        if (tid == 0) g_ml[c] = make_float2(M, L);
    }
    gsync(1);

    const int b = tid & 127, h = tid >> 7;

    // ---------- phase 1: res = vW @ fbar + vb (merge inline, pipelined) ----------
    {
        float2 ml0 = g_ml[2 * b], ml1 = g_ml[2 * b + 1];
        float M  = fmaxf(ml0.x, ml1.x);
        float e0 = __expf(ml0.x - M), e1 = __expf(ml1.x - M);
        float invL = 1.0f / (e0 * ml0.y + e1 * ml1.y);
        float s0 = e0 * invL, s1 = e1 * invL;

        const int n0 = c * 4;
#pragma unroll
        for (int nn = 0; nn < 4; nn++)
            smw[tid * 6 + nn] = (tid < FEAT_) ? vW[(size_t)(n0 + nn) * FEAT_ + tid] : 0.f;
        __syncthreads();

        unsigned long long a1 = 0ull;
        float2 uvA[16], uvB[16];
        auto loadU = [&](float2 (&u)[16], int t) {
#pragma unroll
            for (int i = 0; i < 16; i++)
                u[i] = *(const float2*)(g_uT + (size_t)(t + i) * 256 + 2 * b);
        };
        auto procU = [&](float2 (&u)[16], int t) {
#pragma unroll
            for (int i = 0; i < 16; i++) {
                unsigned long long ap = dup_f32(s0 * u[i].x + s1 * u[i].y);
                fma_x2(a1, ap, *(const unsigned long long*)&smw[(t + i) * 6 + h * 2]);
            }
        };
        // canonical ping-pong: 8 iterations of 32 k
        loadU(uvA, 0);
        for (int tt = 0; tt < 8; tt++) {
            int t = tt * 32;
            loadU(uvB, t + 16);
            procU(uvA, t);
            if (tt < 7) loadU(uvA, t + 32);
            procU(uvB, t + 16);
        }
        float lo, hi; unpack_x2(a1, lo, hi);
        int n = n0 + h * 2;
        g_res[(size_t)n * 128 + b]       = lo + vb[n];
        g_res[(size_t)(n + 1) * 128 + b] = hi + vb[n + 1];
    }
    gsync(2);

    // ---------- phase 2: h1 partials -> atomicAdd (pipelined) ----------
    {
        const int n0 = (c >> 3) * 16, ks = c & 7, k0 = ks * 128;
        if (tid < 128) {
#pragma unroll
            for (int nn = 0; nn < 16; nn++)
                smw[tid * 18 + nn] = W1[(size_t)(n0 + nn) * 1024 + k0 + tid];
        }
        __syncthreads();
        unsigned long long a4[4] = {0ull, 0ull, 0ull, 0ull};
        float avA[16], avB[16];
        auto loadA = [&](float (&a)[16], int t) {
#pragma unroll
            for (int i = 0; i < 16; i++)
                a[i] = g_res[(size_t)(k0 + t + i) * 128 + b];
        };
        auto procA = [&](float (&a)[16], int t) {
#pragma unroll
            for (int i = 0; i < 16; i++) {
                unsigned long long ap = dup_f32(a[i]);
                const float* wp = &smw[(t + i) * 18 + h * 8];
                fma_x2(a4[0], ap, *(const unsigned long long*)(wp + 0));
                fma_x2(a4[1], ap, *(const unsigned long long*)(wp + 2));
                fma_x2(a4[2], ap, *(const unsigned long long*)(wp + 4));
                fma_x2(a4[3], ap, *(const unsigned long long*)(wp + 6));
            }
        };
        loadA(avA, 0);
        for (int tt = 0; tt < 4; tt++) {
            int t = tt * 32;
            loadA(avB, t + 16);
            procA(avA, t);
            if (tt < 3) loadA(avA, t + 32);
            procA(avB, t + 16);
        }
#pragma unroll
        for (int i = 0; i < 4; i++) {
            float lo, hi; unpack_x2(a4[i], lo, hi);
            int n = n0 + h * 8 + 2 * i;
            atomicAdd(&g_h1[(size_t)n * 128 + b], lo);
            atomicAdd(&g_h1[(size_t)(n + 1) * 128 + b], hi);
        }
        __syncthreads();
    }
    gsync(3);

    // ---------- phase 3: h2 partials (relu(h1+b1) inline, pipelined) ----------
    {
        const int n0 = (c >> 3) * 8, ks = c & 7, k0 = ks * 64;
        if (tid < 64) {
#pragma unroll
            for (int nn = 0; nn < 8; nn++)
                smw[tid * 10 + nn] = W2[(size_t)(n0 + nn) * 512 + k0 + tid];
            sqk[tid] = b1[k0 + tid];
        }
        __syncthreads();
        unsigned long long a2[2] = {0ull, 0ull};
        float avA[16], avB[16];
        auto loadH = [&](float (&a)[16], int t) {
#pragma unroll
            for (int i = 0; i < 16; i++)
                a[i] = g_h1[(size_t)(k0 + t + i) * 128 + b];
        };
        auto procH = [&](float (&a)[16], int t) {
#pragma unroll
            for (int i = 0; i < 16; i++) {
                float hv = fmaxf(a[i] + sqk[t + i], 0.f);
                unsigned long long ap = dup_f32(hv);
                const float* wp = &smw[(t + i) * 10 + h * 4];
                fma_x2(a2[0], ap, *(const unsigned long long*)(wp + 0));
                fma_x2(a2[1], ap, *(const unsigned long long*)(wp + 2));
            }
        };
        loadH(avA, 0);
        for (int tt = 0; tt < 2; tt++) {
            int t = tt * 32;
            loadH(avB, t + 16);
            procH(avA, t);
            if (tt < 1) loadH(avA, t + 32);
            procH(avB, t + 16);
        }
#pragma unroll
        for (int i = 0; i < 2; i++) {
            float lo, hi; unpack_x2(a2[i], lo, hi);
            int n = n0 + h * 4 + 2 * i;
            atomicAdd(&g_h2[(size_t)n * 128 + b], lo);
            atomicAdd(&g_h2[(size_t)(n + 1) * 128 + b], hi);
        }
    }

    // ---------- phase 4: last-arriving CTA computes the final layer ----------
    __threadfence();
    __syncthreads();
    if (tid == 0) who = atomicAdd(&g_sync[4], 1);
    __syncthreads();
    if (who == NCTA_ - 1) {
        __threadfence();
        smw[tid]       = W3[tid];
        smw[256 + tid] = W3[256 + tid];
        sqk[tid]       = b2[tid];
        __syncthreads();
        if (tid < 128) {
            float o0 = 0.f, o1 = 0.f;
            float hvA[16], hvB[16];
            auto loadT = [&](float (&a)[16], int t) {
#pragma unroll
                for (int i = 0; i < 16; i++)
                    a[i] = g_h2[(size_t)(t + i) * 128 + tid];
            };
            auto procT = [&](float (&a)[16], int t) {
#pragma unroll
                for (int i = 0; i < 16; i++) {
                    float hh = fmaxf(a[i] + sqk[t + i], 0.f);
                    o0 += hh * smw[t + i];
                    o1 += hh * smw[256 + t + i];
                }
            };
            loadT(hvA, 0);
            for (int tt = 0; tt < 8; tt++) {
                int t = tt * 32;
                loadT(hvB, t + 16);
                procT(hvA, t);
                if (tt < 7) loadT(hvA, t + 32);
                procT(hvB, t + 16);
            }
            ((float2*)out)[tid] = make_float2(o0 + b3[0], o1 + b3[1]);
        }
    }
}

// ===========================================================================
extern "C" void kernel_launch(void* const* d_in, const int* in_sizes, int n_in,
                              void* d_out, int out_size) {
    const float* input = (const float*)d_in[0];
    const float* kW = (const float*)d_in[1];
    // d_in[2] = kb: constant score shift per batch -> cancels in softmax
    const float* vW = (const float*)d_in[3];
    const float* vb = (const float*)d_in[4];
    const float* qW = (const float*)d_in[5];
    const float* qb = (const float*)d_in[6];
    const float* W1 = (const float*)d_in[7];
    const float* b1 = (const float*)d_in[8];
    const float* W2 = (const float*)d_in[9];
    const float* b2 = (const float*)d_in[10];
    const float* W3 = (const float*)d_in[11];
    const float* b3 = (const float*)d_in[12];
    float* out = (float*)d_out;

    void *p_sync, *p_h1, *p_h2;
    cudaGetSymbolAddress(&p_sync, g_sync);
    cudaGetSymbolAddress(&p_h1, g_h1);
    cudaGetSymbolAddress(&p_h2, g_h2);
    cudaMemsetAsync(p_sync, 0, 8 * sizeof(int));
    cudaMemsetAsync(p_h1, 0, 512 * 128 * sizeof(float));
    cudaMemsetAsync(p_h2, 0, 256 * 128 * sizeof(float));

    fused_kernel<<<NCTA_, 256>>>(input, kW, qW, qb, vW, vb,
                                 W1, b1, W2, b2, W3, b3, out);
}

// round 17
// speedup vs baseline: 3.2168x; 1.0788x over previous
#include <cuda_runtime.h>
#include <cuda_bf16.h>
#include <cstdint>
#include <math.h>

// ---------------------------------------------------------------------------
// SimpleModelQ collapsed. ONE fused kernel, ZERO auxiliary graph nodes
// (scratch zeroing + sync-counter reset are done in-kernel).
//   qk[b] = (M @ archi[b] + c)/sqrt(258);  M = kW^T qW, c = kW^T qb
//   (q.kb score shift constant per batch -> cancels in softmax; kb unused)
//   fbar = softmax-weighted feat mean; res=vW@fbar+vb; h1=relu(W1@res+b1);
//   h2=relu(W2@h1+b2); out=W3@h2+b3.
// 256 CTAs x 256 thr, 2 CTAs/SM. Attention: reg double-buffered LDG +
// warp-local online softmax (zero mainloop barriers). MLP: forced-MLP16
// software-pipelined K loops, atomic split-K. 4 gsyncs + who-elected tail.
// g_h1/g_h2 zeroed during phase 1; g_sync reset by the elected tail CTA.
// ---------------------------------------------------------------------------

#define S_     1024
#define LAST_  258
#define FEAT_  255
#define NCTA_  256

// ---- device scratch (zero at module load; self-maintained afterwards) ----
__device__ float4 g_qkp[64 * 256];      // k0 stage-1 partials
__device__ float  g_uT[256 * 256];      // [f][2b+half] unnormalized sums
__device__ float2 g_ml[256];            // [2b+half] (m, l)
__device__ float  g_res[1024 * 128];
__device__ float  g_h1[512 * 128];      // atomic-accumulated; zeroed in phase 1
__device__ float  g_h2[256 * 128];      // atomic-accumulated; zeroed in phase 1
__device__ int    g_sync[8];            // reset by elected tail CTA each launch

__device__ __forceinline__ unsigned long long dup_f32(float a) {
    unsigned long long r;
    asm("mov.b64 %0, {%1, %1};" : "=l"(r) : "f"(a));
    return r;
}
__device__ __forceinline__ void fma_x2(unsigned long long& acc,
                                       unsigned long long a, unsigned long long w) {
    asm("fma.rn.f32x2 %0, %1, %2, %0;" : "+l"(acc) : "l"(a), "l"(w));
}
__device__ __forceinline__ void mul_x2(unsigned long long& d, unsigned long long a,
                                       unsigned long long b) {
    asm("mul.rn.f32x2 %0, %1, %2;" : "=l"(d) : "l"(a), "l"(b));
}
__device__ __forceinline__ void unpack_x2(unsigned long long v, float& lo, float& hi) {
    asm("mov.b64 {%0, %1}, %2;" : "=f"(lo), "=f"(hi) : "l"(v));
}

__device__ __forceinline__ void gsync(int i) {
    __syncthreads();
    if (threadIdx.x == 0) {
        __threadfence();
        atomicAdd(&g_sync[i], 1);
        while (*(volatile int*)&g_sync[i] < NCTA_) { }
        __threadfence();
    }
    __syncthreads();
}

__global__ void __launch_bounds__(256, 2)
fused_kernel(const float* __restrict__ input,
             const float* __restrict__ kW, const float* __restrict__ qW,
             const float* __restrict__ qb,
             const float* __restrict__ vW, const float* __restrict__ vb,
             const float* __restrict__ W1, const float* __restrict__ b1,
             const float* __restrict__ W2, const float* __restrict__ b2,
             const float* __restrict__ W3, const float* __restrict__ b3,
             float* __restrict__ out) {
    __shared__ float qk[264];
    __shared__ float red[8 * 256];
    __shared__ float2 mlw[8];
    __shared__ float sw[64];
    __shared__ __align__(16) float smw[256 * 18];
    __shared__ float sqk[264];
    __shared__ int who;
    const int c    = blockIdx.x;
    const int tid  = threadIdx.x;
    const int lane = tid & 31, w = tid >> 5;
    const int ab = c >> 1, half = c & 1;
    const float* gbase = input + (size_t)ab * S_ * LAST_;
    const float* pbase = gbase + (size_t)(half * 512) * LAST_ + lane * 2;

    // ---------- prefetch attention chunk 0 (overlaps k0 phase) ----------
    unsigned long long xA[4][4], xB[4][4];
    {
        const float* rp = pbase + (size_t)(w * 4) * LAST_;
#pragma unroll
        for (int i = 0; i < 4; i++)
#pragma unroll
            for (int j = 0; j < 4; j++)
                xA[i][j] = *(const unsigned long long*)(rp + (size_t)i * LAST_ + j * 64);
    }
    const float ar0 = gbase[FEAT_ + 0];
    const float ar1 = gbase[FEAT_ + 1];
    const float ar2 = gbase[FEAT_ + 2];

    // ---------- k0 partials (CTAs 0..63, 16 h-rows each) ----------
    if (c < 64) {
        const int h0 = c * 16;
        if (tid < 64) {
            int hh = h0 + (tid >> 2), k = tid & 3;
            sw[tid] = (k < 3) ? qW[hh * 3 + k] : qb[hh];
        }
        __syncthreads();
        float m0 = 0.f, m1 = 0.f, m2 = 0.f, cc2 = 0.f;
        if (tid < FEAT_) {
#pragma unroll
            for (int i = 0; i < 16; i++) {
                float kv = kW[(size_t)(h0 + i) * FEAT_ + tid];
                m0 += kv * sw[i * 4 + 0];
                m1 += kv * sw[i * 4 + 1];
                m2 += kv * sw[i * 4 + 2];
                cc2 += kv * sw[i * 4 + 3];
            }
        }
        g_qkp[c * 256 + tid] = make_float4(m0, m1, m2, cc2);
    }
    gsync(0);

    // ---------- qk vector: every CTA reduces all 64 partials (L2-hot) ----------
    {
        float4 s = make_float4(0.f, 0.f, 0.f, 0.f);
#pragma unroll 8
        for (int p = 0; p < 64; p++) {
            float4 v = g_qkp[p * 256 + tid];
            s.x += v.x; s.y += v.y; s.z += v.z; s.w += v.w;
        }
        float val = (s.x * ar0 + s.y * ar1 + s.z * ar2 + s.w) * rsqrtf(258.0f);
        qk[tid] = (tid < FEAT_) ? val : 0.f;
    }
    __syncthreads();

    unsigned long long q2[4];
#pragma unroll
    for (int j = 0; j < 4; j++)
        q2[j] = *(const unsigned long long*)(qk + j * 64 + lane * 2);

    // ---------- attention mainloop: warp-local softmax, zero barriers ----------
    float m_w = -INFINITY, l_w = 0.f;
    unsigned long long acc[4] = {0ull, 0ull, 0ull, 0ull};

    auto loadc = [&](unsigned long long (&x)[4][4], int ch) {
        const float* rp = pbase + (size_t)(ch * 32 + w * 4) * LAST_;
#pragma unroll
        for (int i = 0; i < 4; i++)
#pragma unroll
            for (int j = 0; j < 4; j++)
                x[i][j] = *(const unsigned long long*)(rp + (size_t)i * LAST_ + j * 64);
    };
    auto process = [&](unsigned long long (&x)[4][4]) {
        float v[4];
#pragma unroll
        for (int i = 0; i < 4; i++) {
            unsigned long long va = 0ull;
#pragma unroll
            for (int j = 0; j < 4; j++) fma_x2(va, x[i][j], q2[j]);
            float lo, hi; unpack_x2(va, lo, hi);
            v[i] = lo + hi;
        }
#pragma unroll
        for (int o = 16; o; o >>= 1) {
#pragma unroll
            for (int i = 0; i < 4; i++)
                v[i] += __shfl_xor_sync(0xffffffffu, v[i], o);
        }
        float mc = fmaxf(fmaxf(v[0], v[1]), fmaxf(v[2], v[3]));
        float mnew  = fmaxf(m_w, mc);
        float alpha = __expf(m_w - mnew);
        float p0 = __expf(v[0] - mnew), p1 = __expf(v[1] - mnew);
        float p2 = __expf(v[2] - mnew), p3 = __expf(v[3] - mnew);
        l_w = l_w * alpha + (p0 + p1) + (p2 + p3);
        m_w = mnew;
        unsigned long long ap = dup_f32(alpha);
#pragma unroll
        for (int j = 0; j < 4; j++) mul_x2(acc[j], acc[j], ap);
        unsigned long long pp0 = dup_f32(p0), pp1 = dup_f32(p1);
        unsigned long long pp2 = dup_f32(p2), pp3 = dup_f32(p3);
#pragma unroll
        for (int j = 0; j < 4; j++) {
            fma_x2(acc[j], pp0, x[0][j]);
            fma_x2(acc[j], pp1, x[1][j]);
            fma_x2(acc[j], pp2, x[2][j]);
            fma_x2(acc[j], pp3, x[3][j]);
        }
    };

    for (int cc = 0; cc < 8; cc++) {
        loadc(xB, 2 * cc + 1);
        process(xA);
        if (cc < 7) loadc(xA, 2 * cc + 2);
        process(xB);
    }

    // ---------- attention epilogue: merge 8 warps -> (M, L, u) ----------
#pragma unroll
    for (int j = 0; j < 4; j++)
        *(unsigned long long*)(red + w * 256 + j * 64 + lane * 2) = acc[j];
    if (lane == 0) mlw[w] = make_float2(m_w, l_w);
    __syncthreads();
    {
        float M = -INFINITY;
#pragma unroll
        for (int ww = 0; ww < 8; ww++) M = fmaxf(M, mlw[ww].x);
        float L = 0.f, u = 0.f;
#pragma unroll
        for (int ww = 0; ww < 8; ww++) {
            float e = __expf(mlw[ww].x - M);
            L += e * mlw[ww].y;
            u += e * red[ww * 256 + tid];
        }
        g_uT[(size_t)tid * 256 + c] = u;       // [f][2b+half]
        if (tid == 0) g_ml[c] = make_float2(M, L);
    }

    // ---------- phase-1 weight tile: load BEFORE the grid sync so the
    //            LDG latency overlaps the attention straggler wait ----------
    {
        const int n0 = c * 4;
#pragma unroll
        for (int nn = 0; nn < 4; nn++)
            smw[tid * 6 + nn] = (tid < FEAT_) ? vW[(size_t)(n0 + nn) * FEAT_ + tid] : 0.f;
    }
    gsync(1);

    const int b = tid & 127, h = tid >> 7;

    // ---------- phase 1: res = vW @ fbar + vb (merge inline, pipelined) ----
    //            also zeroes g_h1/g_h2 for this launch (ordered by gsyncs)
    {
        if (tid < 64) ((float4*)g_h1)[c * 64 + tid] = make_float4(0.f, 0.f, 0.f, 0.f);
        else if (tid < 96) ((float4*)g_h2)[c * 32 + (tid - 64)] = make_float4(0.f, 0.f, 0.f, 0.f);

        float2 ml0 = g_ml[2 * b], ml1 = g_ml[2 * b + 1];
        float M  = fmaxf(ml0.x, ml1.x);
        float e0 = __expf(ml0.x - M), e1 = __expf(ml1.x - M);
        float invL = 1.0f / (e0 * ml0.y + e1 * ml1.y);
        float s0 = e0 * invL, s1 = e1 * invL;

        unsigned long long a1 = 0ull;
        float2 uvA[16], uvB[16];
        auto loadU = [&](float2 (&u)[16], int t) {
#pragma unroll
            for (int i = 0; i < 16; i++)
                u[i] = *(const float2*)(g_uT + (size_t)(t + i) * 256 + 2 * b);
        };
        auto procU = [&](float2 (&u)[16], int t) {
#pragma unroll
            for (int i = 0; i < 16; i++) {
                unsigned long long ap = dup_f32(s0 * u[i].x + s1 * u[i].y);
                fma_x2(a1, ap, *(const unsigned long long*)&smw[(t + i) * 6 + h * 2]);
            }
        };
        loadU(uvA, 0);
        for (int tt = 0; tt < 8; tt++) {
            int t = tt * 32;
            loadU(uvB, t + 16);
            procU(uvA, t);
            if (tt < 7) loadU(uvA, t + 32);
            procU(uvB, t + 16);
        }
        float lo, hi; unpack_x2(a1, lo, hi);
        int n = c * 4 + h * 2;
        g_res[(size_t)n * 128 + b]       = lo + vb[n];
        g_res[(size_t)(n + 1) * 128 + b] = hi + vb[n + 1];
    }
    gsync(2);

    // ---------- phase 2: h1 partials -> atomicAdd (pipelined) ----------
    {
        const int n0 = (c >> 3) * 16, ks = c & 7, k0 = ks * 128;
        if (tid < 128) {
#pragma unroll
            for (int nn = 0; nn < 16; nn++)
                smw[tid * 18 + nn] = W1[(size_t)(n0 + nn) * 1024 + k0 + tid];
        }
        __syncthreads();
        unsigned long long a4[4] = {0ull, 0ull, 0ull, 0ull};
        float avA[16], avB[16];
        auto loadA = [&](float (&a)[16], int t) {
#pragma unroll
            for (int i = 0; i < 16; i++)
                a[i] = g_res[(size_t)(k0 + t + i) * 128 + b];
        };
        auto procA = [&](float (&a)[16], int t) {
#pragma unroll
            for (int i = 0; i < 16; i++) {
                unsigned long long ap = dup_f32(a[i]);
                const float* wp = &smw[(t + i) * 18 + h * 8];
                fma_x2(a4[0], ap, *(const unsigned long long*)(wp + 0));
                fma_x2(a4[1], ap, *(const unsigned long long*)(wp + 2));
                fma_x2(a4[2], ap, *(const unsigned long long*)(wp + 4));
                fma_x2(a4[3], ap, *(const unsigned long long*)(wp + 6));
            }
        };
        loadA(avA, 0);
        for (int tt = 0; tt < 4; tt++) {
            int t = tt * 32;
            loadA(avB, t + 16);
            procA(avA, t);
            if (tt < 3) loadA(avA, t + 32);
            procA(avB, t + 16);
        }
#pragma unroll
        for (int i = 0; i < 4; i++) {
            float lo, hi; unpack_x2(a4[i], lo, hi);
            int n = n0 + h * 8 + 2 * i;
            atomicAdd(&g_h1[(size_t)n * 128 + b], lo);
            atomicAdd(&g_h1[(size_t)(n + 1) * 128 + b], hi);
        }
        __syncthreads();
    }
    gsync(3);

    // ---------- phase 3: h2 partials (relu(h1+b1) inline, pipelined) ----------
    {
        const int n0 = (c >> 3) * 8, ks = c & 7, k0 = ks * 64;
        if (tid < 64) {
#pragma unroll
            for (int nn = 0; nn < 8; nn++)
                smw[tid * 10 + nn] = W2[(size_t)(n0 + nn) * 512 + k0 + tid];
            sqk[tid] = b1[k0 + tid];
        }
        __syncthreads();
        unsigned long long a2[2] = {0ull, 0ull};
        float avA[16], avB[16];
        auto loadH = [&](float (&a)[16], int t) {
#pragma unroll
            for (int i = 0; i < 16; i++)
                a[i] = g_h1[(size_t)(k0 + t + i) * 128 + b];
        };
        auto procH = [&](float (&a)[16], int t) {
#pragma unroll
            for (int i = 0; i < 16; i++) {
                float hv = fmaxf(a[i] + sqk[t + i], 0.f);
                unsigned long long ap = dup_f32(hv);
                const float* wp = &smw[(t + i) * 10 + h * 4];
                fma_x2(a2[0], ap, *(const unsigned long long*)(wp + 0));
                fma_x2(a2[1], ap, *(const unsigned long long*)(wp + 2));
            }
        };
        loadH(avA, 0);
        for (int tt = 0; tt < 2; tt++) {
            int t = tt * 32;
            loadH(avB, t + 16);
            procH(avA, t);
            if (tt < 1) loadH(avA, t + 32);
            procH(avB, t + 16);
        }
#pragma unroll
        for (int i = 0; i < 2; i++) {
            float lo, hi; unpack_x2(a2[i], lo, hi);
            int n = n0 + h * 4 + 2 * i;
            atomicAdd(&g_h2[(size_t)n * 128 + b], lo);
            atomicAdd(&g_h2[(size_t)(n + 1) * 128 + b], hi);
        }
    }

    // ---------- phase 4: last-arriving CTA computes the final layer ----------
    __threadfence();
    __syncthreads();
    if (tid == 0) who = atomicAdd(&g_sync[4], 1);
    __syncthreads();
    if (who == NCTA_ - 1) {
        __threadfence();
        smw[tid]       = W3[tid];
        smw[256 + tid] = W3[256 + tid];
        sqk[tid]       = b2[tid];
        __syncthreads();
        if (tid < 128) {
            float o0 = 0.f, o1 = 0.f;
            float hvA[16], hvB[16];
            auto loadT = [&](float (&a)[16], int t) {
#pragma unroll
                for (int i = 0; i < 16; i++)
                    a[i] = g_h2[(size_t)(t + i) * 128 + tid];
            };
            auto procT = [&](float (&a)[16], int t) {
#pragma unroll
                for (int i = 0; i < 16; i++) {
                    float hh = fmaxf(a[i] + sqk[t + i], 0.f);
                    o0 += hh * smw[t + i];
                    o1 += hh * smw[256 + t + i];
                }
            };
            loadT(hvA, 0);
            for (int tt = 0; tt < 8; tt++) {
                int t = tt * 32;
                loadT(hvB, t + 16);
                procT(hvA, t);
                if (tt < 7) loadT(hvA, t + 32);
                procT(hvB, t + 16);
            }
            ((float2*)out)[tid] = make_float2(o0 + b3[0], o1 + b3[1]);
        }
        // reset grid-sync counters for the next graph replay (this CTA is
        // provably the last one still running; stream order protects us)
        __syncthreads();
        if (tid < 8) g_sync[tid] = 0;
    }
}

// ===========================================================================
extern "C" void kernel_launch(void* const* d_in, const int* in_sizes, int n_in,
                              void* d_out, int out_size) {
    const float* input = (const float*)d_in[0];
    const float* kW = (const float*)d_in[1];
    // d_in[2] = kb: constant score shift per batch -> cancels in softmax
    const float* vW = (const float*)d_in[3];
    const float* vb = (const float*)d_in[4];
    const float* qW = (const float*)d_in[5];
    const float* qb = (const float*)d_in[6];
    const float* W1 = (const float*)d_in[7];
    const float* b1 = (const float*)d_in[8];
    const float* W2 = (const float*)d_in[9];
    const float* b2 = (const float*)d_in[10];
    const float* W3 = (const float*)d_in[11];
    const float* b3 = (const float*)d_in[12];
    float* out = (float*)d_out;

    fused_kernel<<<NCTA_, 256>>>(input, kW, qW, qb, vW, vb,
                                 W1, b1, W2, b2, W3, b3, out);
}